// round 13
// baseline (speedup 1.0000x reference)
#include <cuda_runtime.h>
#include <math.h>

#define BATCH 4
#define NTOK 4096
#define DIMC 192
#define HEADS 8
#define DHEAD 64
#define INNER 512
#define FFD 768
#define MF 266
#define DEPTH 6
#define CPG 24
#define MTOT (BATCH*NTOK)
#define BH (BATCH*HEADS)
#define SPLITK 8

typedef unsigned long long ull;

// ---------------- scratch ----------------
__device__ float g_h [MTOT*DIMC];
__device__ float g_rs[MTOT];
__device__ float g_q [MTOT*INNER];
__device__ float g_k [MTOT*INNER];
__device__ float g_v [MTOT*INNER];
__device__ float g_kp[(long)BH*NTOK*MF];
__device__ float g_ctx [BH*MF*DHEAD];
__device__ float g_ctxp[SPLITK*BH*MF*DHEAD];
__device__ float g_ksum [BH*MF];
__device__ float g_ksump[SPLITK*BH*MF];
__device__ float g_kbm[BH*64];
__device__ float g_kmx[BH];
__device__ float g_ao[MTOT*INNER];
__device__ float g_ff[MTOT*FFD];
__device__ float g_n1[BATCH*DIMC*NTOK];
__device__ float g_n2[BATCH*DIMC*NTOK];
__device__ float g_c7b[BATCH*96*NTOK];
__device__ float g_c5b[BATCH*48*NTOK];
__device__ float g_t1[DIMC*DIMC];
__device__ float g_wc[DIMC*DIMC];

// ---------------- helpers ----------------
__device__ __forceinline__ float geluf(float x){
    return 0.5f*x*(1.0f+erff(x*0.70710678118654752f));
}
__device__ __forceinline__ ull pk2(float lo,float hi){
    ull r; asm("mov.b64 %0,{%1,%2};":"=l"(r):"f"(lo),"f"(hi)); return r;
}
__device__ __forceinline__ void fma2(ull&d, ull a, ull b){
    asm("fma.rn.f32x2 %0,%1,%2,%0;":"+l"(d):"l"(a),"l"(b));
}
__device__ __forceinline__ float2 up2(ull v){
    float2 f; asm("mov.b64 {%0,%1},%2;":"=f"(f.x),"=f"(f.y):"l"(v)); return f;
}
__device__ __forceinline__ unsigned s2u(const void* p){
    return (unsigned)__cvta_generic_to_shared(p);
}
__device__ __forceinline__ void cpa4(unsigned sp, const float* gp){
    asm volatile("cp.async.ca.shared.global [%0],[%1],4;"::"r"(sp),"l"(gp));
}
__device__ __forceinline__ void cpa4p(unsigned sp, const float* gp, int sz){
    asm volatile("cp.async.ca.shared.global [%0],[%1],4,%2;"::"r"(sp),"l"(gp),"r"(sz));
}
__device__ __forceinline__ void cpcommit(){ asm volatile("cp.async.commit_group;"); }
__device__ __forceinline__ void cpwait0(){ asm volatile("cp.async.wait_group 0;"); }
__device__ __forceinline__ void cpwait1(){ asm volatile("cp.async.wait_group 1;"); }

__device__ float brsum(float v, float* sm){
    __syncthreads();
    #pragma unroll
    for(int o=16;o>0;o>>=1) v += __shfl_xor_sync(0xffffffffu, v, o);
    if((threadIdx.x&31)==0) sm[threadIdx.x>>5]=v;
    __syncthreads();
    if(threadIdx.x<32){
        int nw=(blockDim.x+31)>>5;
        float r=(threadIdx.x<nw)? sm[threadIdx.x]:0.f;
        #pragma unroll
        for(int o=16;o>0;o>>=1) r += __shfl_xor_sync(0xffffffffu, r, o);
        if(threadIdx.x==0) sm[0]=r;
    }
    __syncthreads();
    return sm[0];
}

// ---------------- GEMM: 128x64 tile, 128 thr, 8x8 micro, 3-stage cp.async, FFMA2 ----------------
template<int RS,int EPI,int NM>
__global__ void __launch_bounds__(128,4) gemm128(
    const float* __restrict__ A, const float* __restrict__ B,
    float* __restrict__ C, const float* __restrict__ bias,
    const float* __restrict__ rowscale,
    int M,int N,int K,
    long bsA,long bsB,long bsC,
    int rsA,int rsB,int rsC,int csC,
    const float* __restrict__ Bb, float* __restrict__ Cb,
    const float* __restrict__ Bc, float* __restrict__ Cc)
{
    __shared__ __align__(16) float As[3][16][132];
    __shared__ __align__(16) float Bs[3][16][68];
    if(NM==3){
        int z=blockIdx.z;
        if(z==1){B=Bb;C=Cb;}
        else if(z==2){B=Bc;C=Cc;}
    }else{
        int z=blockIdx.z;
        A+=(long)z*bsA; B+=(long)z*bsB; C+=(long)z*bsC;
    }
    int m0=blockIdx.y*128, n0=blockIdx.x*64;
    int tid=threadIdx.x, tx=tid&7, ty=tid>>3;
    int lk=tid&15, lr=tid>>4;
    const float* Ag = A + (long)(m0+lr)*rsA + lk;
    const float* Bg = B + (long)(n0+lr)*rsB + lk;

    ull acc2[8][4];
    #pragma unroll
    for(int a=0;a<8;a++)
    #pragma unroll
    for(int b=0;b<4;b++) acc2[a][b]=0ull;

    int nt=K>>4;
    auto issue=[&](int t,int buf){
        int k0=t<<4;
        #pragma unroll
        for(int e=0;e<16;e++) cpa4(s2u(&As[buf][lk][e*8+lr]), Ag+(long)e*8*rsA+k0);
        #pragma unroll
        for(int e=0;e<8;e++)  cpa4(s2u(&Bs[buf][lk][e*8+lr]), Bg+(long)e*8*rsB+k0);
        cpcommit();
    };
    issue(0,0);
    if(nt>1) issue(1,1);
    for(int t=0;t<nt;t++){
        if(t+1<nt) cpwait1(); else cpwait0();
        __syncthreads();
        if(t+2<nt) issue(t+2,(t+2)%3);
        int buf=t%3;
        #pragma unroll
        for(int k=0;k<16;k++){
            float4 a0=*(const float4*)&As[buf][k][ty*8];
            float4 a1=*(const float4*)&As[buf][k][ty*8+4];
            const ull* bp=(const ull*)&Bs[buf][k][tx*8];
            ull rb[4]={bp[0],bp[1],bp[2],bp[3]};
            float ra[8]={a0.x,a0.y,a0.z,a0.w,a1.x,a1.y,a1.z,a1.w};
            #pragma unroll
            for(int a=0;a<8;a++){
                ull rad=pk2(ra[a],ra[a]);
                #pragma unroll
                for(int b=0;b<4;b++) fma2(acc2[a][b],rad,rb[b]);
            }
        }
    }
    #pragma unroll
    for(int a=0;a<8;a++){
        int gi=m0+ty*8+a;
        float rsa = RS ? rowscale[gi] : 1.f;
        #pragma unroll
        for(int b=0;b<4;b++){
            int gj=n0+tx*8+2*b;
            float2 v=up2(acc2[a][b]);
            if(RS){ v.x*=rsa; v.y*=rsa; }
            if(bias){ v.x+=bias[gj]; v.y+=bias[gj+1]; }
            long o0=(long)gi*rsC+(long)gj*csC;
            long o1=o0+csC;
            if(EPI==1){ v.x=geluf(v.x); v.y=geluf(v.y); }
            if(EPI==2){ v.x+=C[o0]; v.y+=C[o1]; }
            C[o0]=v.x; C[o1]=v.y;
        }
    }
}

// ---------------- k-side FAVOR feature GEMM (writes dd-diag + block max) ----------------
__global__ void __launch_bounds__(272) featgemm(
    const float* __restrict__ Qb, const float* __restrict__ proj,
    float* __restrict__ P, float* __restrict__ bmax)
{
    extern __shared__ __align__(16) float dyn[];
    float* Asb = dyn;                 // [2][16][68]
    float* Bsb = dyn + 2*16*68;       // [2][16][276]
    float* red = dyn + 2*16*68 + 2*16*276;  // [64][36]
    #define ASF(bf,k,i) Asb[(((bf)*16+(k))*68)+(i)]
    #define BSF(bf,k,j) Bsb[(((bf)*16+(k))*276)+(j)]
    int bh=blockIdx.y, b=bh>>3, h=bh&7;
    int m0=blockIdx.x*64;
    const float* A = Qb + ((long)(b*NTOK+m0))*INNER + h*DHEAD;
    int tid=threadIdx.x, tx=tid%34, ty=tid/34;
    ull acc2[8][4];
    #pragma unroll
    for(int a=0;a<8;a++)
    #pragma unroll
    for(int bb=0;bb<4;bb++) acc2[a][bb]=0ull;
    float dsq[8]={};
    auto issue=[&](int t,int buf){
        int k0=t<<4;
        for(int idx=tid;idx<64*16;idx+=272){
            int i=idx>>4,k=idx&15;
            cpa4(s2u(&ASF(buf,k,i)), A+(long)i*INNER+k0+k);
        }
        for(int idx=tid;idx<272*16;idx+=272){
            int j=idx>>4,k=idx&15;
            if(j<MF) cpa4(s2u(&BSF(buf,k,j)), proj+(long)j*DHEAD+k0+k);
            else     cpa4p(s2u(&BSF(buf,k,j)), proj, 0);
        }
        cpcommit();
    };
    issue(0,0);
    cpwait0(); __syncthreads();
    for(int t=0;t<4;t++){
        if(t<3) issue(t+1,(t+1)&1);
        int buf=t&1;
        #pragma unroll
        for(int k=0;k<16;k++){
            float4 a0=*(const float4*)&ASF(buf,k,ty*8);
            float4 a1=*(const float4*)&ASF(buf,k,ty*8+4);
            const ull* bp=(const ull*)&BSF(buf,k,tx*8);
            ull rb[4]={bp[0],bp[1],bp[2],bp[3]};
            float ra[8]={a0.x,a0.y,a0.z,a0.w,a1.x,a1.y,a1.z,a1.w};
            #pragma unroll
            for(int a=0;a<8;a++){
                dsq[a]=fmaf(ra[a],ra[a],dsq[a]);
                ull rad=pk2(ra[a],ra[a]);
                #pragma unroll
                for(int bb=0;bb<4;bb++) fma2(acc2[a][bb],rad,rb[bb]);
            }
        }
        if(t<3){ cpwait0(); __syncthreads(); }
    }
    #pragma unroll
    for(int a=0;a<8;a++){
        float pm=-3.4e38f;
        #pragma unroll
        for(int bb=0;bb<4;bb++){
            int gj=tx*8+2*bb;
            float2 v=up2(acc2[a][bb]);
            if(gj<MF)   pm=fmaxf(pm,v.x);
            if(gj+1<MF) pm=fmaxf(pm,v.y);
        }
        red[(ty*8+a)*36+tx]=pm;
    }
    __syncthreads();
    if(tid<64){
        float m=-3.4e38f;
        #pragma unroll
        for(int j=0;j<34;j++) m=fmaxf(m,red[tid*36+j]);
        red[tid*36+34]=m;
    }
    __syncthreads();
    if(tid==0){
        float m=-3.4e38f;
        for(int r=0;r<64;r++) m=fmaxf(m,red[r*36+34]);
        bmax[bh*64+blockIdx.x]=m;
    }
    const float dn=0.35355339059327373f;       // 64^-0.25
    #pragma unroll
    for(int a=0;a<8;a++){
        int row=ty*8+a;
        float diag=0.0625f*dsq[a];
        float* op=P+((long)bh*NTOK+m0+row)*MF;
        #pragma unroll
        for(int bb=0;bb<4;bb++){
            int gj=tx*8+2*bb;
            float2 v=up2(acc2[a][bb]);
            if(gj<MF)   op[gj]  =dn*v.x-diag;
            if(gj+1<MF) op[gj+1]=dn*v.y-diag;
        }
    }
    #undef ASF
    #undef BSF
}

__global__ void kgmax_kernel(){
    int bh=blockIdx.x, t=threadIdx.x;
    float m=fmaxf(g_kbm[bh*64+t], g_kbm[bh*64+32+t]);
    #pragma unroll
    for(int o=16;o>0;o>>=1) m=fmaxf(m,__shfl_xor_sync(0xffffffffu,m,o));
    if(t==0) g_kmx[bh]=0.35355339059327373f*m;
}

// ---------------- fused q-features + attention-out + denom: qattn ----------------
// Phase 1: q feature GEMM (dd, diag, rowmax) -> SQ smem (exp'd), denom via ksum.
// Phase 2: out[64][64] = SQ[64][266] . ctx[266][64], /denom -> g_ao.
__global__ void __launch_bounds__(272) qattn(
    const float* __restrict__ Qb, const float* __restrict__ proj)
{
    extern __shared__ __align__(16) float dyn[];
    float* SQ  = dyn;                         // 64 x 276 = 17664 floats
    float* Asb = dyn;                         // phase1: aliases SQ[0..2175]
    float* Bsb = dyn + 2176;                  // phase1: 2*16*276=8832 (ends 11008<17664)
    float* cbuf= dyn + 17664;                 // 2*16*68 = 2176
    float* red = dyn + 17664 + 2176;          // 64*36 = 2304
    float* kss = dyn + 17664 + 2176 + 2304;   // 272
    #define ASF(bf,k,i) Asb[(((bf)*16+(k))*68)+(i)]
    #define BSF(bf,k,j) Bsb[(((bf)*16+(k))*276)+(j)]
    #define CBF(bf,k,d) cbuf[(((bf)*16+(k))*68)+(d)]
    int bh=blockIdx.y, b=bh>>3, h=bh&7;
    int m0=blockIdx.x*64;
    const float* A = Qb + ((long)(b*NTOK+m0))*INNER + h*DHEAD;
    const float* ctxb = g_ctx + (long)bh*MF*DHEAD;
    int tid=threadIdx.x, tx=tid%34, ty=tid/34;
    ull acc2[8][4];
    #pragma unroll
    for(int a=0;a<8;a++)
    #pragma unroll
    for(int bb=0;bb<4;bb++) acc2[a][bb]=0ull;
    float dsq[8]={};
    auto issue=[&](int t,int buf){
        int k0=t<<4;
        for(int idx=tid;idx<64*16;idx+=272){
            int i=idx>>4,k=idx&15;
            cpa4(s2u(&ASF(buf,k,i)), A+(long)i*INNER+k0+k);
        }
        for(int idx=tid;idx<272*16;idx+=272){
            int j=idx>>4,k=idx&15;
            if(j<MF) cpa4(s2u(&BSF(buf,k,j)), proj+(long)j*DHEAD+k0+k);
            else     cpa4p(s2u(&BSF(buf,k,j)), proj, 0);
        }
        cpcommit();
    };
    // ksum into smem (rides along with first group)
    cpa4p(s2u(&kss[tid]), g_ksum+bh*MF+((tid<MF)?tid:0), (tid<MF)?4:0);
    issue(0,0);
    cpwait0(); __syncthreads();
    for(int t=0;t<4;t++){
        if(t<3) issue(t+1,(t+1)&1);
        int buf=t&1;
        #pragma unroll
        for(int k=0;k<16;k++){
            float4 a0=*(const float4*)&ASF(buf,k,ty*8);
            float4 a1=*(const float4*)&ASF(buf,k,ty*8+4);
            const ull* bp=(const ull*)&BSF(buf,k,tx*8);
            ull rb[4]={bp[0],bp[1],bp[2],bp[3]};
            float ra[8]={a0.x,a0.y,a0.z,a0.w,a1.x,a1.y,a1.z,a1.w};
            #pragma unroll
            for(int a=0;a<8;a++){
                dsq[a]=fmaf(ra[a],ra[a],dsq[a]);
                ull rad=pk2(ra[a],ra[a]);
                #pragma unroll
                for(int bb=0;bb<4;bb++) fma2(acc2[a][bb],rad,rb[bb]);
            }
        }
        if(t<3){ cpwait0(); __syncthreads(); }
    }
    // rowmax
    #pragma unroll
    for(int a=0;a<8;a++){
        float pm=-3.4e38f;
        #pragma unroll
        for(int bb=0;bb<4;bb++){
            int gj=tx*8+2*bb;
            float2 v=up2(acc2[a][bb]);
            if(gj<MF)   pm=fmaxf(pm,v.x);
            if(gj+1<MF) pm=fmaxf(pm,v.y);
        }
        red[(ty*8+a)*36+tx]=pm;
    }
    __syncthreads();
    if(tid<64){
        float m=-3.4e38f;
        #pragma unroll
        for(int j=0;j<34;j++) m=fmaxf(m,red[tid*36+j]);
        red[tid*36+34]=m;
    }
    __syncthreads();
    // exp'd q features -> SQ (aliases phase1 buffers; all threads past GEMM loop), denom partials
    const float dn=0.35355339059327373f;       // 64^-0.25
    const float ratio=0.06131393394849658f;    // 266^-0.5
    #pragma unroll
    for(int a=0;a<8;a++){
        int row=ty*8+a;
        float diag=0.0625f*dsq[a];
        float mx=dn*red[row*36+34];
        float dpart=0.f;
        #pragma unroll
        for(int bb=0;bb<4;bb++){
            int gj=tx*8+2*bb;
            float2 v=up2(acc2[a][bb]);
            float q0=(gj<MF)?   ratio*(expf(dn*v.x-diag-mx)+1e-4f):0.f;
            float q1=(gj+1<MF)? ratio*(expf(dn*v.y-diag-mx)+1e-4f):0.f;
            SQ[row*276+gj]=q0;
            SQ[row*276+gj+1]=q1;
            dpart=fmaf(q0,kss[gj],dpart);
            dpart=fmaf(q1,kss[gj+1],dpart);
        }
        red[row*36+tx]=dpart;      // cols 0..33 (col 34 untouched)
    }
    __syncthreads();
    if(tid<64){
        float s=0.f;
        #pragma unroll
        for(int j=0;j<34;j++) s+=red[tid*36+j];
        red[tid*36+35]=1.0f/s;
    }
    __syncthreads();
    // ---- phase 2: out = SQ . ctx ----
    auto issueC=[&](int t){
        int buf=t&1, mc=t*16;
        for(int idx=tid;idx<16*64;idx+=272){
            int kk=idx>>6, d=idx&63;
            int m=mc+kk;
            cpa4p(s2u(&CBF(buf,kk,d)), ctxb+(long)m*DHEAD+d, (m<MF)?4:0);
        }
        cpcommit();
    };
    ull acc[2][4];
    #pragma unroll
    for(int i2=0;i2<2;i2++)
    #pragma unroll
    for(int j=0;j<4;j++) acc[i2][j]=0ull;
    int ry=tid>>3, txc=tid&7;
    issueC(0);
    cpwait0(); __syncthreads();
    for(int t=0;t<17;t++){
        if(t+1<17) issueC(t+1);
        int buf=t&1;
        if(tid<256){
            #pragma unroll
            for(int kk=0;kk<16;kk++){
                int m=t*16+kk;
                float s0=SQ[ry*276+m];
                float s1=SQ[(ry+32)*276+m];
                const ull* cp2=(const ull*)&CBF(buf,kk,txc*8);
                ull c0=cp2[0],c1=cp2[1],c2=cp2[2],c3=cp2[3];
                ull p0=pk2(s0,s0), p1=pk2(s1,s1);
                fma2(acc[0][0],p0,c0); fma2(acc[0][1],p0,c1);
                fma2(acc[0][2],p0,c2); fma2(acc[0][3],p0,c3);
                fma2(acc[1][0],p1,c0); fma2(acc[1][1],p1,c1);
                fma2(acc[1][2],p1,c2); fma2(acc[1][3],p1,c3);
            }
        }
        if(t+1<17){ cpwait0(); __syncthreads(); }
    }
    if(tid<256){
        float inv0=red[ry*36+35], inv1=red[(ry+32)*36+35];
        float* op0=g_ao+((long)(b*NTOK+m0+ry))*INNER+h*DHEAD+txc*8;
        float* op1=g_ao+((long)(b*NTOK+m0+ry+32))*INNER+h*DHEAD+txc*8;
        #pragma unroll
        for(int j=0;j<4;j++){
            float2 v0=up2(acc[0][j]), v1=up2(acc[1][j]);
            op0[2*j]=v0.x*inv0; op0[2*j+1]=v0.y*inv0;
            op1[2*j]=v1.x*inv1; op1[2*j+1]=v1.y*inv1;
        }
    }
    #undef ASF
    #undef BSF
    #undef CBF
}

// ---------------- context GEMM (exp(kp)^T . v) + fused exp + ksum, split-K=8 ----------------
__global__ void __launch_bounds__(128) ctxgemm(){
    __shared__ __align__(16) float As[2][16][68];
    __shared__ __align__(16) float Bs[3][16][68];
    int mt=blockIdx.x, bh=blockIdx.y, kc=blockIdx.z;
    int b=bh>>3, h=bh&7;
    int m0=mt*64;
    const float gm=g_kmx[bh];
    const float ratio=0.06131393394849658f;
    const float* Abase=g_kp+((long)bh*NTOK+(long)kc*(NTOK/SPLITK))*MF;
    const float* Bbase=g_v+((long)b*NTOK+(long)kc*(NTOK/SPLITK))*INNER+h*DHEAD;
    int tid=threadIdx.x, tx=tid&7, ty=tid>>3;
    float rA[8];
    ull acc2[4][4];
    #pragma unroll
    for(int a=0;a<4;a++)
    #pragma unroll
    for(int bb=0;bb<4;bb++) acc2[a][bb]=0ull;
    float dsum[4]={};
    auto loadA=[&](int k0){
        #pragma unroll
        for(int e=0;e<8;e++){int idx=e*128+tid;int i=idx&63,k=idx>>6;
            int gi=m0+i;
            rA[e]=(gi<MF)?Abase[(long)(k0+k)*MF+gi]:0.f;}
    };
    auto issueB=[&](int t){
        int k0=t*16, buf=t%3;
        #pragma unroll
        for(int e=0;e<8;e++){int idx=e*128+tid;int j=idx&63,k=idx>>6;
            cpa4(s2u(&Bs[buf][k][j]), Bbase+(long)(k0+k)*INNER+j);}
        cpcommit();
    };
    const int NT=(NTOK/SPLITK)/16;
    loadA(0);
    issueB(0); issueB(1);
    for(int t=0;t<NT;t++){
        #pragma unroll
        for(int e=0;e<8;e++){int idx=e*128+tid;
            As[t&1][idx>>6][idx&63]=ratio*(expf(rA[e]-gm)+1e-4f);}
        if(t+1<NT) loadA((t+1)*16);
        if(t+1<NT) cpwait1(); else cpwait0();
        __syncthreads();
        if(t+2<NT) issueB(t+2);
        int bbuf=t%3, abuf=t&1;
        #pragma unroll
        for(int k=0;k<16;k++){
            float4 a0=*(const float4*)&As[abuf][k][ty*4];
            const ull* bp=(const ull*)&Bs[bbuf][k][tx*8];
            ull rb[4]={bp[0],bp[1],bp[2],bp[3]};
            float ra[4]={a0.x,a0.y,a0.z,a0.w};
            #pragma unroll
            for(int a=0;a<4;a++){
                dsum[a]+=ra[a];
                ull rad=pk2(ra[a],ra[a]);
                #pragma unroll
                for(int bb=0;bb<4;bb++) fma2(acc2[a][bb],rad,rb[bb]);
            }
        }
        __syncthreads();
    }
    float* cp=g_ctxp+(long)(kc*BH+bh)*MF*DHEAD;
    #pragma unroll
    for(int a=0;a<4;a++){
        int m=m0+ty*4+a; if(m>=MF) continue;
        #pragma unroll
        for(int bb=0;bb<4;bb++){
            float2 v=up2(acc2[a][bb]);
            cp[(long)m*DHEAD+tx*8+2*bb]  =v.x;
            cp[(long)m*DHEAD+tx*8+2*bb+1]=v.y;
        }
        if(tx==0) g_ksump[(kc*BH+bh)*MF+m]=dsum[a];
    }
}

__global__ void ctxreduce_kernel(){
    int idx=blockIdx.x*256+threadIdx.x;
    const int tot=BH*MF*DHEAD;
    if(idx<tot){
        float s=0.f;
        #pragma unroll
        for(int c=0;c<SPLITK;c++) s+=g_ctxp[(long)c*tot+idx];
        g_ctx[idx]=s;
    }
    if(idx<BH*MF){
        float s=0.f;
        #pragma unroll
        for(int c=0;c<SPLITK;c++) s+=g_ksump[c*BH*MF+idx];
        g_ksum[idx]=s;
    }
}

// ---------------- small kernels ----------------
__global__ void embed_kernel(const float* __restrict__ x, const float* __restrict__ w,
                             const float* __restrict__ bvec, const float* __restrict__ pos){
    int n=blockIdx.x, d=threadIdx.x;
    int p=n&(NTOK-1);
    float acc=bvec[d]+pos[(long)p*DIMC+d];
    acc=fmaf(x[(long)n*3+0], w[d*3+0], acc);
    acc=fmaf(x[(long)n*3+1], w[d*3+1], acc);
    acc=fmaf(x[(long)n*3+2], w[d*3+2], acc);
    g_h[(long)n*DIMC+d]=acc;
}

__global__ void rownorm_kernel(const float* __restrict__ in, float* __restrict__ rs,
                               const float* __restrict__ gptr){
    int r=blockIdx.x*8+(threadIdx.x>>5);
    int lane=threadIdx.x&31;
    const float* row=in+(long)r*DIMC;
    float s=0.f;
    #pragma unroll
    for(int j=0;j<6;j++){ float v=row[lane+j*32]; s=fmaf(v,v,s); }
    #pragma unroll
    for(int o=16;o>0;o>>=1) s+=__shfl_xor_sync(0xffffffffu,s,o);
    if(lane==0){
        float norm=sqrtf(s*(1.0f/DIMC));
        rs[r]=gptr[0]/fmaxf(norm,1e-5f);
    }
}

__global__ void mm192(const float* __restrict__ A, const float* __restrict__ B,
                      float* __restrict__ C){
    int idx=blockIdx.x*256+threadIdx.x;
    if(idx>=DIMC*DIMC) return;
    int i=idx/DIMC, j=idx%DIMC;
    float s=0.f;
    for(int k=0;k<DIMC;k++) s=fmaf(A[i*DIMC+k],B[k*DIMC+j],s);
    C[idx]=s;
}

__global__ void groupnorm_kernel(const float* __restrict__ gamma, const float* __restrict__ beta){
    __shared__ float red[32];
    int b=blockIdx.x>>3, g=blockIdx.x&7;
    long base=((long)b*DIMC+g*CPG)*NTOK;
    float s=0.f, ss=0.f;
    for(int i=threadIdx.x;i<CPG*NTOK;i+=blockDim.x){
        float v=g_n1[base+i]; s+=v; ss=fmaf(v,v,ss);
    }
    s=brsum(s,red);
    ss=brsum(ss,red);
    const float cnt=(float)(CPG*NTOK);
    float mean=s/cnt;
    float var=ss/cnt-mean*mean;
    float inv=rsqrtf(var+1e-5f);
    for(int i=threadIdx.x;i<CPG*NTOK;i+=blockDim.x){
        int c=g*CPG+i/NTOK;
        float v=(g_n1[base+i]-mean)*inv;
        g_n1[base+i]=v*gamma[c]+beta[c];
    }
}

// circular grouped conv: 32x16 tile, 4 px/thread, OCB outputs (paired f32x2), fused GELU
template<int KS,int ICPG,int OCPG,int OCB>
__global__ void __launch_bounds__(128) circconv4(
    const float* __restrict__ in, const float* __restrict__ w,
    const float* __restrict__ bias, float* __restrict__ out, int inC, int outC)
{
    const int P=KS/2, TWX=16+2*P, TH=32+2*P;
    const int OH=OCB/2;
    __shared__ float patch[TH*TWX];
    __shared__ ull wk2[OH*KS*KS];
    int tile=blockIdx.x, og=blockIdx.y, b=blockIdx.z;
    int oc0=og*OCB;
    int gbase=(oc0/OCPG)*ICPG;
    int ty0=(tile&1)*32, tx0=(tile>>1)*16;
    int tid=threadIdx.x;
    int tx=tid&15, ty=tid>>4;
    ull acc2[4][OH];
    #pragma unroll
    for(int r=0;r<4;r++)
    #pragma unroll
    for(int o=0;o<OH;o++) acc2[r][o]=0ull;
    for(int ic=0;ic<ICPG;ic++){
        const float* ip=in+((long)(b*inC+gbase+ic))*NTOK;
        __syncthreads();
        for(int idx=tid;idx<TH*TWX;idx+=128){
            int py=idx/TWX, px=idx%TWX;
            int sy=(ty0+py-P)&63, sx=(tx0+px-P)&63;
            patch[idx]=ip[sy*64+sx];
        }
        for(int idx=tid;idx<OH*KS*KS;idx+=128){
            int o=idx/(KS*KS), t=idx%(KS*KS);
            float wlo=w[((long)(oc0+2*o  )*ICPG+ic)*KS*KS+t];
            float whi=w[((long)(oc0+2*o+1)*ICPG+ic)*KS*KS+t];
            wk2[idx]=pk2(wlo,whi);
        }
        __syncthreads();
        for(int ky=0;ky<KS;ky++){
            #pragma unroll
            for(int kx=0;kx<KS;kx++){
                float p0=patch[(ty   +ky)*TWX+tx+kx];
                float p1=patch[(ty+8 +ky)*TWX+tx+kx];
                float p2=patch[(ty+16+ky)*TWX+tx+kx];
                float p3=patch[(ty+24+ky)*TWX+tx+kx];
                ull pd0=pk2(p0,p0), pd1=pk2(p1,p1), pd2=pk2(p2,p2), pd3=pk2(p3,p3);
                #pragma unroll
                for(int o=0;o<OH;o++){
                    ull wv=wk2[o*KS*KS+ky*KS+kx];
                    fma2(acc2[0][o],pd0,wv);
                    fma2(acc2[1][o],pd1,wv);
                    fma2(acc2[2][o],pd2,wv);
                    fma2(acc2[3][o],pd3,wv);
                }
            }
        }
    }
    #pragma unroll
    for(int o=0;o<OH;o++){
        float blo=bias[oc0+2*o], bhi=bias[oc0+2*o+1];
        long cb0=((long)(b*outC+oc0+2*o  ))*NTOK;
        long cb1=((long)(b*outC+oc0+2*o+1))*NTOK;
        #pragma unroll
        for(int r=0;r<4;r++){
            float2 v=up2(acc2[r][o]);
            int px=(ty0+ty+8*r)*64+tx0+tx;
            out[cb0+px]=geluf(v.x+blo);
            out[cb1+px]=geluf(v.y+bhi);
        }
    }
}

__global__ void conv1_kernel(const float* __restrict__ w, const float* __restrict__ bias,
                             float* __restrict__ out){
    int idx=blockIdx.x*blockDim.x+threadIdx.x;
    if(idx>=MTOT) return;
    int b=idx>>12, p=idx&(NTOK-1);
    const float* base=g_c5b+(long)b*48*NTOK+p;
    #pragma unroll
    for(int c=0;c<3;c++){
        float acc=bias[c];
        #pragma unroll
        for(int ic=0;ic<48;ic++) acc=fmaf(w[c*48+ic], base[(long)ic*NTOK], acc);
        out[(long)idx*3+c]=acc;
    }
}

// ---------------- host ----------------
extern "C" void kernel_launch(void* const* d_in, const int* in_sizes, int n_in,
                              void* d_out, int out_size) {
    (void)in_sizes; (void)n_in; (void)out_size;
    const float* x        =(const float*)d_in[0];
    const float* to_in_w  =(const float*)d_in[1];
    const float* to_in_b  =(const float*)d_in[2];
    const float* pos      =(const float*)d_in[3];
    const float* proj     =(const float*)d_in[4];
    const float* sn_attn_g=(const float*)d_in[5];
    const float* wq       =(const float*)d_in[6];
    const float* wk       =(const float*)d_in[7];
    const float* wv       =(const float*)d_in[8];
    const float* wo       =(const float*)d_in[9];
    const float* bo       =(const float*)d_in[10];
    const float* sn_ff_g  =(const float*)d_in[11];
    const float* w1       =(const float*)d_in[12];
    const float* b1       =(const float*)d_in[13];
    const float* w2       =(const float*)d_in[14];
    const float* b2       =(const float*)d_in[15];
    const float* expand_w =(const float*)d_in[16];
    const float* fwd_w    =(const float*)d_in[17];
    const float* dec_w    =(const float*)d_in[18];
    const float* dec_b    =(const float*)d_in[19];
    const float* gn_g     =(const float*)d_in[20];
    const float* gn_b     =(const float*)d_in[21];
    const float* c9w      =(const float*)d_in[22];
    const float* c9b      =(const float*)d_in[23];
    const float* c7w      =(const float*)d_in[24];
    const float* c7b      =(const float*)d_in[25];
    const float* c5w      =(const float*)d_in[26];
    const float* c5b      =(const float*)d_in[27];
    const float* c1w      =(const float*)d_in[28];
    const float* c1b      =(const float*)d_in[29];
    float* out=(float*)d_out;

    void* p;
    cudaGetSymbolAddress(&p,g_h);   float* h  =(float*)p;
    cudaGetSymbolAddress(&p,g_rs);  float* rs =(float*)p;
    cudaGetSymbolAddress(&p,g_q);   float* q  =(float*)p;
    cudaGetSymbolAddress(&p,g_k);   float* k  =(float*)p;
    cudaGetSymbolAddress(&p,g_v);   float* v  =(float*)p;
    cudaGetSymbolAddress(&p,g_kp);  float* kp =(float*)p;
    cudaGetSymbolAddress(&p,g_kbm); float* kbm=(float*)p;
    cudaGetSymbolAddress(&p,g_ao);  float* ao =(float*)p;
    cudaGetSymbolAddress(&p,g_ff);  float* ff =(float*)p;
    cudaGetSymbolAddress(&p,g_n1);  float* n1 =(float*)p;
    cudaGetSymbolAddress(&p,g_n2);  float* n2 =(float*)p;
    cudaGetSymbolAddress(&p,g_c7b); float* c7buf=(float*)p;
    cudaGetSymbolAddress(&p,g_c5b); float* c5buf=(float*)p;
    cudaGetSymbolAddress(&p,g_t1);  float* t1 =(float*)p;
    cudaGetSymbolAddress(&p,g_wc);  float* wc =(float*)p;

    const int FEAT_SMEM = (2*16*68 + 2*16*276 + 64*36)*4;  // 53248
    cudaFuncSetAttribute(featgemm, cudaFuncAttributeMaxDynamicSharedMemorySize, FEAT_SMEM);
    const int QATTN_SMEM = (17664 + 2176 + 2304 + 272)*4;  // 89664
    cudaFuncSetAttribute(qattn, cudaFuncAttributeMaxDynamicSharedMemorySize, QATTN_SMEM);

    embed_kernel<<<MTOT,DIMC>>>(x,to_in_w,to_in_b,pos);
    // precompute Wc = dec_w . fwd_w . expand_w  (weights only)
    mm192<<<(DIMC*DIMC+255)/256,256>>>(fwd_w,expand_w,t1);
    mm192<<<(DIMC*DIMC+255)/256,256>>>(dec_w,t1,wc);

    for(int i=0;i<DEPTH;i++){
        const float* wq_l=wq+(long)i*INNER*DIMC;
        const float* wk_l=wk+(long)i*INNER*DIMC;
        const float* wv_l=wv+(long)i*INNER*DIMC;
        const float* proj_l=proj+(long)i*MF*DHEAD;

        // ---- attention ----
        rownorm_kernel<<<MTOT/8,256>>>(h,rs,sn_attn_g+i);
        gemm128<1,0,3><<<dim3(8,128,3),128>>>(h,wq_l,q,nullptr,rs, MTOT,INNER,DIMC,
                 0,0,0, DIMC,DIMC,INNER,1, wk_l,k, wv_l,v);
        // k-side first (qattn needs ksum + ctx)
        featgemm<<<dim3(64,BH),272,FEAT_SMEM>>>(k,proj_l,kp,kbm);
        kgmax_kernel<<<BH,32>>>();
        ctxgemm<<<dim3(5,BH,SPLITK),128>>>();
        ctxreduce_kernel<<<(BH*MF*DHEAD+255)/256,256>>>();
        // fused q-features + attention out + denom
        qattn<<<dim3(64,BH),272,QATTN_SMEM>>>(q,proj_l);
        gemm128<0,2,1><<<dim3(3,128,1),128>>>(ao,wo+(long)i*DIMC*INNER,h,bo+(long)i*DIMC,nullptr,
                 MTOT,DIMC,INNER, 0,0,0, INNER,INNER,DIMC,1, nullptr,nullptr,nullptr,nullptr);
        // ---- feed-forward ----
        rownorm_kernel<<<MTOT/8,256>>>(h,rs,sn_ff_g+i);
        gemm128<1,1,1><<<dim3(12,128,1),128>>>(h,w1+(long)i*FFD*DIMC,ff,b1+(long)i*FFD,rs,
                 MTOT,FFD,DIMC, 0,0,0, DIMC,DIMC,FFD,1, nullptr,nullptr,nullptr,nullptr);
        gemm128<0,2,1><<<dim3(3,128,1),128>>>(ff,w2+(long)i*DIMC*FFD,h,b2+(long)i*DIMC,nullptr,
                 MTOT,DIMC,FFD, 0,0,0, FFD,FFD,DIMC,1, nullptr,nullptr,nullptr,nullptr);
    }

    // ---- decoder: single fused linear h -> n1 (NCHW) ----
    gemm128<0,0,1><<<dim3(3,32,BATCH),128>>>(h,wc,n1,dec_b,nullptr,
             NTOK,DIMC,DIMC,
             (long)NTOK*DIMC,0,(long)DIMC*NTOK,
             DIMC,DIMC,1,NTOK, nullptr,nullptr,nullptr,nullptr);
    groupnorm_kernel<<<32,512>>>(gn_g,gn_b);
    circconv4<9,24,24,12><<<dim3(8,16,BATCH),128>>>(n1,c9w,c9b,n2,192,192);
    circconv4<7,24,12,6><<<dim3(8,16,BATCH),128>>>(n2,c7w,c7b,c7buf,192,96);
    circconv4<5,12,6,6><<<dim3(8,8,BATCH),128>>>(c7buf,c5w,c5b,c5buf,96,48);
    conv1_kernel<<<(MTOT+127)/128,128>>>(c1w,c1b,out);
}

// round 14
// speedup vs baseline: 1.7411x; 1.7411x over previous
#include <cuda_runtime.h>
#include <math.h>

#define BATCH 4
#define NTOK 4096
#define DIMC 192
#define HEADS 8
#define DHEAD 64
#define INNER 512
#define FFD 768
#define MF 266
#define DEPTH 6
#define CPG 24
#define MTOT (BATCH*NTOK)
#define BH (BATCH*HEADS)
#define SPLITK 8

typedef unsigned long long ull;

// ---------------- scratch ----------------
__device__ float g_h [MTOT*DIMC];
__device__ float g_rs[MTOT];
__device__ float g_q [MTOT*INNER];
__device__ float g_k [MTOT*INNER];
__device__ float g_v [MTOT*INNER];
__device__ float g_qp[(long)BH*NTOK*MF];
__device__ float g_kp[(long)BH*NTOK*MF];
__device__ float g_ctx [BH*MF*DHEAD];
__device__ float g_ctxp[SPLITK*BH*MF*DHEAD];
__device__ float g_ksum [BH*MF];
__device__ float g_ksump[SPLITK*BH*MF];
__device__ float g_kbm[BH*64];
__device__ float g_kmx[BH];
__device__ float g_ao[MTOT*INNER];
__device__ float g_ff[MTOT*FFD];
__device__ float g_n1[BATCH*DIMC*NTOK];
__device__ float g_n2[BATCH*DIMC*NTOK];
__device__ float g_c7b[BATCH*96*NTOK];
__device__ float g_c5b[BATCH*48*NTOK];
__device__ float g_t1[DIMC*DIMC];
__device__ float g_wc[DIMC*DIMC];

// ---------------- helpers ----------------
__device__ __forceinline__ float geluf(float x){
    return 0.5f*x*(1.0f+erff(x*0.70710678118654752f));
}
__device__ __forceinline__ ull pk2(float lo,float hi){
    ull r; asm("mov.b64 %0,{%1,%2};":"=l"(r):"f"(lo),"f"(hi)); return r;
}
__device__ __forceinline__ void fma2(ull&d, ull a, ull b){
    asm("fma.rn.f32x2 %0,%1,%2,%0;":"+l"(d):"l"(a),"l"(b));
}
__device__ __forceinline__ float2 up2(ull v){
    float2 f; asm("mov.b64 {%0,%1},%2;":"=f"(f.x),"=f"(f.y):"l"(v)); return f;
}
__device__ __forceinline__ unsigned s2u(const void* p){
    return (unsigned)__cvta_generic_to_shared(p);
}
__device__ __forceinline__ void cpa4(unsigned sp, const float* gp){
    asm volatile("cp.async.ca.shared.global [%0],[%1],4;"::"r"(sp),"l"(gp));
}
__device__ __forceinline__ void cpa4p(unsigned sp, const float* gp, int sz){
    asm volatile("cp.async.ca.shared.global [%0],[%1],4,%2;"::"r"(sp),"l"(gp),"r"(sz));
}
__device__ __forceinline__ void cpcommit(){ asm volatile("cp.async.commit_group;"); }
__device__ __forceinline__ void cpwait0(){ asm volatile("cp.async.wait_group 0;"); }
__device__ __forceinline__ void cpwait1(){ asm volatile("cp.async.wait_group 1;"); }

__device__ float brsum(float v, float* sm){
    __syncthreads();
    #pragma unroll
    for(int o=16;o>0;o>>=1) v += __shfl_xor_sync(0xffffffffu, v, o);
    if((threadIdx.x&31)==0) sm[threadIdx.x>>5]=v;
    __syncthreads();
    if(threadIdx.x<32){
        int nw=(blockDim.x+31)>>5;
        float r=(threadIdx.x<nw)? sm[threadIdx.x]:0.f;
        #pragma unroll
        for(int o=16;o>0;o>>=1) r += __shfl_xor_sync(0xffffffffu, r, o);
        if(threadIdx.x==0) sm[0]=r;
    }
    __syncthreads();
    return sm[0];
}

// ---------------- GEMM: 128x64 tile, 128 thr, 8x8 micro, 3-stage cp.async, FFMA2 ----------------
// Callers guarantee M%128==0, N%64==0, K%16==0.
// C = (rs.)A.B^T: A(i,k)=A[i*rsA+k], B(j,k)=B[j*rsB+k], C(i,j)=C[i*rsC+j*csC]
// Rowscale (RS) applied in EPILOGUE.
// EPI: 0 = +bias ; 1 = gelu(+bias) ; 2 = C += (+bias)
// NM==3: blockIdx.z selects (B,C) among three pairs (shared A) — fused QKV.
template<int RS,int EPI,int NM>
__global__ void __launch_bounds__(128,4) gemm128(
    const float* __restrict__ A, const float* __restrict__ B,
    float* __restrict__ C, const float* __restrict__ bias,
    const float* __restrict__ rowscale,
    int M,int N,int K,
    long bsA,long bsB,long bsC,
    int rsA,int rsB,int rsC,int csC,
    const float* __restrict__ Bb, float* __restrict__ Cb,
    const float* __restrict__ Bc, float* __restrict__ Cc)
{
    __shared__ __align__(16) float As[3][16][132];
    __shared__ __align__(16) float Bs[3][16][68];
    if(NM==3){
        int z=blockIdx.z;
        if(z==1){B=Bb;C=Cb;}
        else if(z==2){B=Bc;C=Cc;}
    }else{
        int z=blockIdx.z;
        A+=(long)z*bsA; B+=(long)z*bsB; C+=(long)z*bsC;
    }
    int m0=blockIdx.y*128, n0=blockIdx.x*64;
    int tid=threadIdx.x, tx=tid&7, ty=tid>>3;
    int lk=tid&15, lr=tid>>4;
    const float* Ag = A + (long)(m0+lr)*rsA + lk;
    const float* Bg = B + (long)(n0+lr)*rsB + lk;

    ull acc2[8][4];
    #pragma unroll
    for(int a=0;a<8;a++)
    #pragma unroll
    for(int b=0;b<4;b++) acc2[a][b]=0ull;

    int nt=K>>4;
    auto issue=[&](int t,int buf){
        int k0=t<<4;
        #pragma unroll
        for(int e=0;e<16;e++) cpa4(s2u(&As[buf][lk][e*8+lr]), Ag+(long)e*8*rsA+k0);
        #pragma unroll
        for(int e=0;e<8;e++)  cpa4(s2u(&Bs[buf][lk][e*8+lr]), Bg+(long)e*8*rsB+k0);
        cpcommit();
    };
    issue(0,0);
    if(nt>1) issue(1,1);
    for(int t=0;t<nt;t++){
        if(t+1<nt) cpwait1(); else cpwait0();
        __syncthreads();
        if(t+2<nt) issue(t+2,(t+2)%3);
        int buf=t%3;
        #pragma unroll
        for(int k=0;k<16;k++){
            float4 a0=*(const float4*)&As[buf][k][ty*8];
            float4 a1=*(const float4*)&As[buf][k][ty*8+4];
            const ull* bp=(const ull*)&Bs[buf][k][tx*8];
            ull rb[4]={bp[0],bp[1],bp[2],bp[3]};
            float ra[8]={a0.x,a0.y,a0.z,a0.w,a1.x,a1.y,a1.z,a1.w};
            #pragma unroll
            for(int a=0;a<8;a++){
                ull rad=pk2(ra[a],ra[a]);
                #pragma unroll
                for(int b=0;b<4;b++) fma2(acc2[a][b],rad,rb[b]);
            }
        }
    }
    #pragma unroll
    for(int a=0;a<8;a++){
        int gi=m0+ty*8+a;
        float rsa = RS ? rowscale[gi] : 1.f;
        #pragma unroll
        for(int b=0;b<4;b++){
            int gj=n0+tx*8+2*b;
            float2 v=up2(acc2[a][b]);
            if(RS){ v.x*=rsa; v.y*=rsa; }
            if(bias){ v.x+=bias[gj]; v.y+=bias[gj+1]; }
            long o0=(long)gi*rsC+(long)gj*csC;
            long o1=o0+csC;
            if(EPI==1){ v.x=geluf(v.x); v.y=geluf(v.y); }
            if(EPI==2){ v.x+=C[o0]; v.y+=C[o1]; }
            C[o0]=v.x; C[o1]=v.y;
        }
    }
}

// ---------------- fused FAVOR feature GEMM, cp.async dbuf (dynamic smem) ----------------
template<int ISQ>
__global__ void __launch_bounds__(272) featgemm(
    const float* __restrict__ Qb, const float* __restrict__ proj,
    float* __restrict__ P, float* __restrict__ bmax)
{
    extern __shared__ __align__(16) float dyn[];
    float* Asb = dyn;                 // [2][16][68]
    float* Bsb = dyn + 2*16*68;       // [2][16][276]
    float* red = dyn + 2*16*68 + 2*16*276;  // [64][36]
    #define ASF(bf,k,i) Asb[(((bf)*16+(k))*68)+(i)]
    #define BSF(bf,k,j) Bsb[(((bf)*16+(k))*276)+(j)]
    int bh=blockIdx.y, b=bh>>3, h=bh&7;
    int m0=blockIdx.x*64;
    const float* A = Qb + ((long)(b*NTOK+m0))*INNER + h*DHEAD;
    int tid=threadIdx.x, tx=tid%34, ty=tid/34;
    ull acc2[8][4];
    #pragma unroll
    for(int a=0;a<8;a++)
    #pragma unroll
    for(int bb=0;bb<4;bb++) acc2[a][bb]=0ull;
    float dsq[8]={};
    auto issue=[&](int t,int buf){
        int k0=t<<4;
        for(int idx=tid;idx<64*16;idx+=272){
            int i=idx>>4,k=idx&15;
            cpa4(s2u(&ASF(buf,k,i)), A+(long)i*INNER+k0+k);
        }
        for(int idx=tid;idx<272*16;idx+=272){
            int j=idx>>4,k=idx&15;
            if(j<MF) cpa4(s2u(&BSF(buf,k,j)), proj+(long)j*DHEAD+k0+k);
            else     cpa4p(s2u(&BSF(buf,k,j)), proj, 0);
        }
        cpcommit();
    };
    issue(0,0);
    cpwait0(); __syncthreads();
    for(int t=0;t<4;t++){
        if(t<3) issue(t+1,(t+1)&1);
        int buf=t&1;
        #pragma unroll
        for(int k=0;k<16;k++){
            float4 a0=*(const float4*)&ASF(buf,k,ty*8);
            float4 a1=*(const float4*)&ASF(buf,k,ty*8+4);
            const ull* bp=(const ull*)&BSF(buf,k,tx*8);
            ull rb[4]={bp[0],bp[1],bp[2],bp[3]};
            float ra[8]={a0.x,a0.y,a0.z,a0.w,a1.x,a1.y,a1.z,a1.w};
            #pragma unroll
            for(int a=0;a<8;a++){
                dsq[a]=fmaf(ra[a],ra[a],dsq[a]);
                ull rad=pk2(ra[a],ra[a]);
                #pragma unroll
                for(int bb=0;bb<4;bb++) fma2(acc2[a][bb],rad,rb[bb]);
            }
        }
        if(t<3){ cpwait0(); __syncthreads(); }
    }
    #pragma unroll
    for(int a=0;a<8;a++){
        float pm=-3.4e38f;
        #pragma unroll
        for(int bb=0;bb<4;bb++){
            int gj=tx*8+2*bb;
            float2 v=up2(acc2[a][bb]);
            if(gj<MF)   pm=fmaxf(pm,v.x);
            if(gj+1<MF) pm=fmaxf(pm,v.y);
        }
        red[(ty*8+a)*36+tx]=pm;
    }
    __syncthreads();
    if(tid<64){
        float m=-3.4e38f;
        #pragma unroll
        for(int j=0;j<34;j++) m=fmaxf(m,red[tid*36+j]);
        red[tid*36+34]=m;
    }
    __syncthreads();
    if(!ISQ && tid==0){
        float m=-3.4e38f;
        for(int r=0;r<64;r++) m=fmaxf(m,red[r*36+34]);
        bmax[bh*64+blockIdx.x]=m;
    }
    const float dn=0.35355339059327373f;       // 64^-0.25
    const float ratio=0.06131393394849658f;    // 266^-0.5
    #pragma unroll
    for(int a=0;a<8;a++){
        int row=ty*8+a;
        float diag=0.0625f*dsq[a];
        float mx=dn*red[row*36+34];
        float* op=P+((long)bh*NTOK+m0+row)*MF;
        #pragma unroll
        for(int bb=0;bb<4;bb++){
            int gj=tx*8+2*bb;
            float2 v=up2(acc2[a][bb]);
            if(gj<MF){
                float dd=dn*v.x;
                op[gj]= ISQ ? ratio*(expf(dd-diag-mx)+1e-4f) : (dd-diag);
            }
            if(gj+1<MF){
                float dd=dn*v.y;
                op[gj+1]= ISQ ? ratio*(expf(dd-diag-mx)+1e-4f) : (dd-diag);
            }
        }
    }
    #undef ASF
    #undef BSF
}

__global__ void kgmax_kernel(){
    int bh=blockIdx.x, t=threadIdx.x;
    float m=fmaxf(g_kbm[bh*64+t], g_kbm[bh*64+32+t]);
    #pragma unroll
    for(int o=16;o>0;o>>=1) m=fmaxf(m,__shfl_xor_sync(0xffffffffu,m,o));
    if(t==0) g_kmx[bh]=0.35355339059327373f*m;
}

// ---------------- context GEMM (exp(kp)^T . v) + fused exp + ksum, split-K=8 ----------------
// B via 3-stage cp.async ring; A register-staged (exp applied once per element).
__global__ void __launch_bounds__(128) ctxgemm(){
    __shared__ __align__(16) float As[2][16][68];
    __shared__ __align__(16) float Bs[3][16][68];
    int mt=blockIdx.x, bh=blockIdx.y, kc=blockIdx.z;
    int b=bh>>3, h=bh&7;
    int m0=mt*64;
    const float gm=g_kmx[bh];
    const float ratio=0.06131393394849658f;
    const float* Abase=g_kp+((long)bh*NTOK+(long)kc*(NTOK/SPLITK))*MF;
    const float* Bbase=g_v+((long)b*NTOK+(long)kc*(NTOK/SPLITK))*INNER+h*DHEAD;
    int tid=threadIdx.x, tx=tid&7, ty=tid>>3;
    float rA[8];
    ull acc2[4][4];
    #pragma unroll
    for(int a=0;a<4;a++)
    #pragma unroll
    for(int bb=0;bb<4;bb++) acc2[a][bb]=0ull;
    float dsum[4]={};
    auto loadA=[&](int k0){
        #pragma unroll
        for(int e=0;e<8;e++){int idx=e*128+tid;int i=idx&63,k=idx>>6;
            int gi=m0+i;
            rA[e]=(gi<MF)?Abase[(long)(k0+k)*MF+gi]:0.f;}
    };
    auto issueB=[&](int t){
        int k0=t*16, buf=t%3;
        #pragma unroll
        for(int e=0;e<8;e++){int idx=e*128+tid;int j=idx&63,k=idx>>6;
            cpa4(s2u(&Bs[buf][k][j]), Bbase+(long)(k0+k)*INNER+j);}
        cpcommit();
    };
    const int NT=(NTOK/SPLITK)/16;
    loadA(0);
    issueB(0); issueB(1);
    for(int t=0;t<NT;t++){
        #pragma unroll
        for(int e=0;e<8;e++){int idx=e*128+tid;
            As[t&1][idx>>6][idx&63]=ratio*(expf(rA[e]-gm)+1e-4f);}
        if(t+1<NT) loadA((t+1)*16);
        if(t+1<NT) cpwait1(); else cpwait0();
        __syncthreads();
        if(t+2<NT) issueB(t+2);
        int bbuf=t%3, abuf=t&1;
        #pragma unroll
        for(int k=0;k<16;k++){
            float4 a0=*(const float4*)&As[abuf][k][ty*4];
            const ull* bp=(const ull*)&Bs[bbuf][k][tx*8];
            ull rb[4]={bp[0],bp[1],bp[2],bp[3]};
            float ra[4]={a0.x,a0.y,a0.z,a0.w};
            #pragma unroll
            for(int a=0;a<4;a++){
                dsum[a]+=ra[a];
                ull rad=pk2(ra[a],ra[a]);
                #pragma unroll
                for(int bb=0;bb<4;bb++) fma2(acc2[a][bb],rad,rb[bb]);
            }
        }
        __syncthreads();
    }
    float* cp=g_ctxp+(long)(kc*BH+bh)*MF*DHEAD;
    #pragma unroll
    for(int a=0;a<4;a++){
        int m=m0+ty*4+a; if(m>=MF) continue;
        #pragma unroll
        for(int bb=0;bb<4;bb++){
            float2 v=up2(acc2[a][bb]);
            cp[(long)m*DHEAD+tx*8+2*bb]  =v.x;
            cp[(long)m*DHEAD+tx*8+2*bb+1]=v.y;
        }
        if(tx==0) g_ksump[(kc*BH+bh)*MF+m]=dsum[a];
    }
}

__global__ void ctxreduce_kernel(){
    int idx=blockIdx.x*256+threadIdx.x;
    const int tot=BH*MF*DHEAD;
    if(idx<tot){
        float s=0.f;
        #pragma unroll
        for(int c=0;c<SPLITK;c++) s+=g_ctxp[(long)c*tot+idx];
        g_ctx[idx]=s;
    }
    if(idx<BH*MF){
        float s=0.f;
        #pragma unroll
        for(int c=0;c<SPLITK;c++) s+=g_ksump[c*BH*MF+idx];
        g_ksum[idx]=s;
    }
}

// ---------------- attention out GEMM (qp . ctx) + fused denom, cp.async dbuf, FFMA2 ----------------
__global__ void __launch_bounds__(128,3) attnout(){
    __shared__ __align__(16) float As[2][16][132];
    __shared__ __align__(16) float Bs[2][16][68];
    __shared__ float Kss[2][16];
    int mt=blockIdx.x, bh=blockIdx.y;
    int b=bh>>3, h=bh&7;
    int m0=mt*128;
    const float* Abase=g_qp+((long)bh*NTOK+m0)*MF;
    const float* Bbase=g_ctx+(long)bh*MF*DHEAD;
    const float* ks=g_ksum+bh*MF;
    int tid=threadIdx.x, tx=tid&7, ty=tid>>3;
    int lk=tid&15, lr=tid>>4;
    ull acc2[8][4];
    #pragma unroll
    for(int a=0;a<8;a++)
    #pragma unroll
    for(int bb=0;bb<4;bb++) acc2[a][bb]=0ull;
    float dden[8]={};
    auto loadT=[&](int k0,int buf){
        int gk=k0+lk;
        int sz=(gk<MF)?4:0;
        int gkc=(gk<MF)?gk:(MF-1);
        #pragma unroll
        for(int e=0;e<16;e++)
            cpa4p(s2u(&As[buf][lk][e*8+lr]), &Abase[(long)(e*8+lr)*MF+gkc], sz);
        #pragma unroll
        for(int e=0;e<8;e++)
            cpa4p(s2u(&Bs[buf][lk][e*8+lr]), &Bbase[(long)gkc*DHEAD+e*8+lr], sz);
        if(tid<16){
            int g2=k0+tid;
            int s2=(g2<MF)?4:0;
            int g2c=(g2<MF)?g2:(MF-1);
            cpa4p(s2u(&Kss[buf][tid]), &ks[g2c], s2);
        }
        cpcommit();
    };
    const int nt=(MF+15)>>4;   // 17
    loadT(0,0);
    cpwait0(); __syncthreads();
    for(int t=0;t<nt;t++){
        if(t+1<nt) loadT((t+1)<<4,(t+1)&1);
        int buf=t&1;
        #pragma unroll
        for(int k=0;k<16;k++){
            float4 a0=*(const float4*)&As[buf][k][ty*8];
            float4 a1=*(const float4*)&As[buf][k][ty*8+4];
            const ull* bp=(const ull*)&Bs[buf][k][tx*8];
            ull rb[4]={bp[0],bp[1],bp[2],bp[3]};
            float ksv=Kss[buf][k];
            float ra[8]={a0.x,a0.y,a0.z,a0.w,a1.x,a1.y,a1.z,a1.w};
            #pragma unroll
            for(int a=0;a<8;a++){
                dden[a]=fmaf(ra[a],ksv,dden[a]);
                ull rad=pk2(ra[a],ra[a]);
                #pragma unroll
                for(int bb=0;bb<4;bb++) fma2(acc2[a][bb],rad,rb[bb]);
            }
        }
        if(t+1<nt){ cpwait0(); __syncthreads(); }
    }
    float* op=g_ao+((long)(b*NTOK+m0))*INNER+h*DHEAD;
    #pragma unroll
    for(int a=0;a<8;a++){
        float inv=1.0f/dden[a];
        int row=ty*8+a;
        #pragma unroll
        for(int bb=0;bb<4;bb++){
            float2 v=up2(acc2[a][bb]);
            op[(long)row*INNER+tx*8+2*bb]  =v.x*inv;
            op[(long)row*INNER+tx*8+2*bb+1]=v.y*inv;
        }
    }
}

// ---------------- small kernels ----------------
__global__ void embed_kernel(const float* __restrict__ x, const float* __restrict__ w,
                             const float* __restrict__ bvec, const float* __restrict__ pos){
    int n=blockIdx.x, d=threadIdx.x;
    int p=n&(NTOK-1);
    float acc=bvec[d]+pos[(long)p*DIMC+d];
    acc=fmaf(x[(long)n*3+0], w[d*3+0], acc);
    acc=fmaf(x[(long)n*3+1], w[d*3+1], acc);
    acc=fmaf(x[(long)n*3+2], w[d*3+2], acc);
    g_h[(long)n*DIMC+d]=acc;
}

__global__ void rownorm_kernel(const float* __restrict__ in, float* __restrict__ rs,
                               const float* __restrict__ gptr){
    int r=blockIdx.x*8+(threadIdx.x>>5);
    int lane=threadIdx.x&31;
    const float* row=in+(long)r*DIMC;
    float s=0.f;
    #pragma unroll
    for(int j=0;j<6;j++){ float v=row[lane+j*32]; s=fmaf(v,v,s); }
    #pragma unroll
    for(int o=16;o>0;o>>=1) s+=__shfl_xor_sync(0xffffffffu,s,o);
    if(lane==0){
        float norm=sqrtf(s*(1.0f/DIMC));
        rs[r]=gptr[0]/fmaxf(norm,1e-5f);
    }
}

__global__ void mm192(const float* __restrict__ A, const float* __restrict__ B,
                      float* __restrict__ C){
    int idx=blockIdx.x*256+threadIdx.x;
    if(idx>=DIMC*DIMC) return;
    int i=idx/DIMC, j=idx%DIMC;
    float s=0.f;
    for(int k=0;k<DIMC;k++) s=fmaf(A[i*DIMC+k],B[k*DIMC+j],s);
    C[idx]=s;
}

__global__ void groupnorm_kernel(const float* __restrict__ gamma, const float* __restrict__ beta){
    __shared__ float red[32];
    int b=blockIdx.x>>3, g=blockIdx.x&7;
    long base=((long)b*DIMC+g*CPG)*NTOK;
    float s=0.f, ss=0.f;
    for(int i=threadIdx.x;i<CPG*NTOK;i+=blockDim.x){
        float v=g_n1[base+i]; s+=v; ss=fmaf(v,v,ss);
    }
    s=brsum(s,red);
    ss=brsum(ss,red);
    const float cnt=(float)(CPG*NTOK);
    float mean=s/cnt;
    float var=ss/cnt-mean*mean;
    float inv=rsqrtf(var+1e-5f);
    for(int i=threadIdx.x;i<CPG*NTOK;i+=blockDim.x){
        int c=g*CPG+i/NTOK;
        float v=(g_n1[base+i]-mean)*inv;
        g_n1[base+i]=v*gamma[c]+beta[c];
    }
}

// circular grouped conv: 32x16 tile, 4 px/thread, OCB outputs (paired f32x2), fused GELU
template<int KS,int ICPG,int OCPG,int OCB>
__global__ void __launch_bounds__(128) circconv4(
    const float* __restrict__ in, const float* __restrict__ w,
    const float* __restrict__ bias, float* __restrict__ out, int inC, int outC)
{
    const int P=KS/2, TWX=16+2*P, TH=32+2*P;
    const int OH=OCB/2;
    __shared__ float patch[TH*TWX];
    __shared__ ull wk2[OH*KS*KS];
    int tile=blockIdx.x, og=blockIdx.y, b=blockIdx.z;
    int oc0=og*OCB;
    int gbase=(oc0/OCPG)*ICPG;
    int ty0=(tile&1)*32, tx0=(tile>>1)*16;
    int tid=threadIdx.x;
    int tx=tid&15, ty=tid>>4;
    ull acc2[4][OH];
    #pragma unroll
    for(int r=0;r<4;r++)
    #pragma unroll
    for(int o=0;o<OH;o++) acc2[r][o]=0ull;
    for(int ic=0;ic<ICPG;ic++){
        const float* ip=in+((long)(b*inC+gbase+ic))*NTOK;
        __syncthreads();
        for(int idx=tid;idx<TH*TWX;idx+=128){
            int py=idx/TWX, px=idx%TWX;
            int sy=(ty0+py-P)&63, sx=(tx0+px-P)&63;
            patch[idx]=ip[sy*64+sx];
        }
        for(int idx=tid;idx<OH*KS*KS;idx+=128){
            int o=idx/(KS*KS), t=idx%(KS*KS);
            float wlo=w[((long)(oc0+2*o  )*ICPG+ic)*KS*KS+t];
            float whi=w[((long)(oc0+2*o+1)*ICPG+ic)*KS*KS+t];
            wk2[idx]=pk2(wlo,whi);
        }
        __syncthreads();
        for(int ky=0;ky<KS;ky++){
            #pragma unroll
            for(int kx=0;kx<KS;kx++){
                float p0=patch[(ty   +ky)*TWX+tx+kx];
                float p1=patch[(ty+8 +ky)*TWX+tx+kx];
                float p2=patch[(ty+16+ky)*TWX+tx+kx];
                float p3=patch[(ty+24+ky)*TWX+tx+kx];
                ull pd0=pk2(p0,p0), pd1=pk2(p1,p1), pd2=pk2(p2,p2), pd3=pk2(p3,p3);
                #pragma unroll
                for(int o=0;o<OH;o++){
                    ull wv=wk2[o*KS*KS+ky*KS+kx];
                    fma2(acc2[0][o],pd0,wv);
                    fma2(acc2[1][o],pd1,wv);
                    fma2(acc2[2][o],pd2,wv);
                    fma2(acc2[3][o],pd3,wv);
                }
            }
        }
    }
    #pragma unroll
    for(int o=0;o<OH;o++){
        float blo=bias[oc0+2*o], bhi=bias[oc0+2*o+1];
        long cb0=((long)(b*outC+oc0+2*o  ))*NTOK;
        long cb1=((long)(b*outC+oc0+2*o+1))*NTOK;
        #pragma unroll
        for(int r=0;r<4;r++){
            float2 v=up2(acc2[r][o]);
            int px=(ty0+ty+8*r)*64+tx0+tx;
            out[cb0+px]=geluf(v.x+blo);
            out[cb1+px]=geluf(v.y+bhi);
        }
    }
}

__global__ void conv1_kernel(const float* __restrict__ w, const float* __restrict__ bias,
                             float* __restrict__ out){
    int idx=blockIdx.x*blockDim.x+threadIdx.x;
    if(idx>=MTOT) return;
    int b=idx>>12, p=idx&(NTOK-1);
    const float* base=g_c5b+(long)b*48*NTOK+p;
    #pragma unroll
    for(int c=0;c<3;c++){
        float acc=bias[c];
        #pragma unroll
        for(int ic=0;ic<48;ic++) acc=fmaf(w[c*48+ic], base[(long)ic*NTOK], acc);
        out[(long)idx*3+c]=acc;
    }
}

// ---------------- host ----------------
extern "C" void kernel_launch(void* const* d_in, const int* in_sizes, int n_in,
                              void* d_out, int out_size) {
    (void)in_sizes; (void)n_in; (void)out_size;
    const float* x        =(const float*)d_in[0];
    const float* to_in_w  =(const float*)d_in[1];
    const float* to_in_b  =(const float*)d_in[2];
    const float* pos      =(const float*)d_in[3];
    const float* proj     =(const float*)d_in[4];
    const float* sn_attn_g=(const float*)d_in[5];
    const float* wq       =(const float*)d_in[6];
    const float* wk       =(const float*)d_in[7];
    const float* wv       =(const float*)d_in[8];
    const float* wo       =(const float*)d_in[9];
    const float* bo       =(const float*)d_in[10];
    const float* sn_ff_g  =(const float*)d_in[11];
    const float* w1       =(const float*)d_in[12];
    const float* b1       =(const float*)d_in[13];
    const float* w2       =(const float*)d_in[14];
    const float* b2       =(const float*)d_in[15];
    const float* expand_w =(const float*)d_in[16];
    const float* fwd_w    =(const float*)d_in[17];
    const float* dec_w    =(const float*)d_in[18];
    const float* dec_b    =(const float*)d_in[19];
    const float* gn_g     =(const float*)d_in[20];
    const float* gn_b     =(const float*)d_in[21];
    const float* c9w      =(const float*)d_in[22];
    const float* c9b      =(const float*)d_in[23];
    const float* c7w      =(const float*)d_in[24];
    const float* c7b      =(const float*)d_in[25];
    const float* c5w      =(const float*)d_in[26];
    const float* c5b      =(const float*)d_in[27];
    const float* c1w      =(const float*)d_in[28];
    const float* c1b      =(const float*)d_in[29];
    float* out=(float*)d_out;

    void* p;
    cudaGetSymbolAddress(&p,g_h);   float* h  =(float*)p;
    cudaGetSymbolAddress(&p,g_rs);  float* rs =(float*)p;
    cudaGetSymbolAddress(&p,g_q);   float* q  =(float*)p;
    cudaGetSymbolAddress(&p,g_k);   float* k  =(float*)p;
    cudaGetSymbolAddress(&p,g_v);   float* v  =(float*)p;
    cudaGetSymbolAddress(&p,g_qp);  float* qp =(float*)p;
    cudaGetSymbolAddress(&p,g_kp);  float* kp =(float*)p;
    cudaGetSymbolAddress(&p,g_kbm); float* kbm=(float*)p;
    cudaGetSymbolAddress(&p,g_ao);  float* ao =(float*)p;
    cudaGetSymbolAddress(&p,g_ff);  float* ff =(float*)p;
    cudaGetSymbolAddress(&p,g_n1);  float* n1 =(float*)p;
    cudaGetSymbolAddress(&p,g_n2);  float* n2 =(float*)p;
    cudaGetSymbolAddress(&p,g_c7b); float* c7buf=(float*)p;
    cudaGetSymbolAddress(&p,g_c5b); float* c5buf=(float*)p;
    cudaGetSymbolAddress(&p,g_t1);  float* t1 =(float*)p;
    cudaGetSymbolAddress(&p,g_wc);  float* wc =(float*)p;

    const int FEAT_SMEM = (2*16*68 + 2*16*276 + 64*36)*4;  // 53248
    cudaFuncSetAttribute(featgemm<1>, cudaFuncAttributeMaxDynamicSharedMemorySize, FEAT_SMEM);
    cudaFuncSetAttribute(featgemm<0>, cudaFuncAttributeMaxDynamicSharedMemorySize, FEAT_SMEM);

    embed_kernel<<<MTOT,DIMC>>>(x,to_in_w,to_in_b,pos);
    // precompute Wc = dec_w . fwd_w . expand_w  (weights only)
    mm192<<<(DIMC*DIMC+255)/256,256>>>(fwd_w,expand_w,t1);
    mm192<<<(DIMC*DIMC+255)/256,256>>>(dec_w,t1,wc);

    for(int i=0;i<DEPTH;i++){
        const float* wq_l=wq+(long)i*INNER*DIMC;
        const float* wk_l=wk+(long)i*INNER*DIMC;
        const float* wv_l=wv+(long)i*INNER*DIMC;
        const float* proj_l=proj+(long)i*MF*DHEAD;

        // ---- attention ----
        rownorm_kernel<<<MTOT/8,256>>>(h,rs,sn_attn_g+i);
        gemm128<1,0,3><<<dim3(8,128,3),128>>>(h,wq_l,q,nullptr,rs, MTOT,INNER,DIMC,
                 0,0,0, DIMC,DIMC,INNER,1, wk_l,k, wv_l,v);
        featgemm<1><<<dim3(64,BH),272,FEAT_SMEM>>>(q,proj_l,qp,kbm);
        featgemm<0><<<dim3(64,BH),272,FEAT_SMEM>>>(k,proj_l,kp,kbm);
        kgmax_kernel<<<BH,32>>>();
        ctxgemm<<<dim3(5,BH,SPLITK),128>>>();
        ctxreduce_kernel<<<(BH*MF*DHEAD+255)/256,256>>>();
        attnout<<<dim3(32,BH),128>>>();
        gemm128<0,2,1><<<dim3(3,128,1),128>>>(ao,wo+(long)i*DIMC*INNER,h,bo+(long)i*DIMC,nullptr,
                 MTOT,DIMC,INNER, 0,0,0, INNER,INNER,DIMC,1, nullptr,nullptr,nullptr,nullptr);
        // ---- feed-forward ----
        rownorm_kernel<<<MTOT/8,256>>>(h,rs,sn_ff_g+i);
        gemm128<1,1,1><<<dim3(12,128,1),128>>>(h,w1+(long)i*FFD*DIMC,ff,b1+(long)i*FFD,rs,
                 MTOT,FFD,DIMC, 0,0,0, DIMC,DIMC,FFD,1, nullptr,nullptr,nullptr,nullptr);
        gemm128<0,2,1><<<dim3(3,128,1),128>>>(ff,w2+(long)i*DIMC*FFD,h,b2+(long)i*DIMC,nullptr,
                 MTOT,DIMC,FFD, 0,0,0, FFD,FFD,DIMC,1, nullptr,nullptr,nullptr,nullptr);
    }

    // ---- decoder: single fused linear h -> n1 (NCHW) ----
    gemm128<0,0,1><<<dim3(3,32,BATCH),128>>>(h,wc,n1,dec_b,nullptr,
             NTOK,DIMC,DIMC,
             (long)NTOK*DIMC,0,(long)DIMC*NTOK,
             DIMC,DIMC,1,NTOK, nullptr,nullptr,nullptr,nullptr);
    groupnorm_kernel<<<32,512>>>(gn_g,gn_b);
    circconv4<9,24,24,12><<<dim3(8,16,BATCH),128>>>(n1,c9w,c9b,n2,192,192);
    circconv4<7,24,12,6><<<dim3(8,16,BATCH),128>>>(n2,c7w,c7b,c7buf,192,96);
    circconv4<5,12,6,6><<<dim3(8,8,BATCH),128>>>(c7buf,c5w,c5b,c5buf,96,48);
    conv1_kernel<<<(MTOT+127)/128,128>>>(c1w,c1b,out);
}